// round 11
// baseline (speedup 1.0000x reference)
#include <cuda_runtime.h>
#include <cuda_fp16.h>
#include <cstdint>
#include <math.h>

#define N_NODES 100000
#define N_EDGES 1000000
#define SCAN_BLK 98               // ceil(100000 / 1024)

// ---------------- scratch (static device globals; no allocation) ----------------
__device__ __half g_H[(size_t)N_NODES * 128];   // [N][128] fp16 : x@W0 | x@W1
__device__ __half g_T[(size_t)N_NODES * 64];    // [N][64]  fp16 : A h1
__device__ float  g_deg1[N_NODES];              // A 1

// CSR build scratch (g_cnt zero at load; re-zeroed by scan1 each call)
__device__ int   g_cnt[N_NODES];
__device__ int   g_cur[N_NODES];                // scatter cursors (init = row ptr)
__device__ int   g_ptr[N_NODES + 1];            // row_ptr (exclusive)
__device__ int   g_blk[128];                    // block sums for scan
__device__ unsigned long long g_edge[N_EDGES];  // packed {val_bits:32 | col:32}

// ---------------- histogram of rows ----------------
__global__ void hist_kernel(const int* __restrict__ ei) {
    const int stride = gridDim.x * blockDim.x;
    const int4* R4 = (const int4*)ei;
    for (int i = blockIdx.x * blockDim.x + threadIdx.x; i < N_EDGES / 4; i += stride) {
        int4 r = __ldg(&R4[i]);
        atomicAdd(&g_cnt[r.x], 1);
        atomicAdd(&g_cnt[r.y], 1);
        atomicAdd(&g_cnt[r.z], 1);
        atomicAdd(&g_cnt[r.w], 1);
    }
}

// ---------------- scan stage 1: per-block exclusive scan; also re-zero g_cnt --------
__global__ __launch_bounds__(256) void scan1_kernel() {
    __shared__ int sh[256];
    const int t = threadIdx.x;
    const int base = blockIdx.x * 1024 + t * 4;
    int c0 = (base + 0 < N_NODES) ? g_cnt[base + 0] : 0;
    int c1 = (base + 1 < N_NODES) ? g_cnt[base + 1] : 0;
    int c2 = (base + 2 < N_NODES) ? g_cnt[base + 2] : 0;
    int c3 = (base + 3 < N_NODES) ? g_cnt[base + 3] : 0;
    if (base + 0 < N_NODES) g_cnt[base + 0] = 0;
    if (base + 1 < N_NODES) g_cnt[base + 1] = 0;
    if (base + 2 < N_NODES) g_cnt[base + 2] = 0;
    if (base + 3 < N_NODES) g_cnt[base + 3] = 0;
    int tsum = c0 + c1 + c2 + c3;
    sh[t] = tsum;
    __syncthreads();
    for (int off = 1; off < 256; off <<= 1) {
        int v = (t >= off) ? sh[t - off] : 0;
        __syncthreads();
        if (t >= off) sh[t] += v;
        __syncthreads();
    }
    int excl = (t > 0) ? sh[t - 1] : 0;
    if (t == 255) g_blk[blockIdx.x] = sh[255];
    if (base + 0 < N_NODES) g_ptr[base + 0] = excl;
    if (base + 1 < N_NODES) g_ptr[base + 1] = excl + c0;
    if (base + 2 < N_NODES) g_ptr[base + 2] = excl + c0 + c1;
    if (base + 3 < N_NODES) g_ptr[base + 3] = excl + c0 + c1 + c2;
}

// ---- scan stage 2+3 fused: redundant warp-scan of block sums + add offsets; ----
// ---- also initializes scatter cursors g_cur = row ptr.                      ----
__global__ __launch_bounds__(256) void scan3_kernel() {
    __shared__ int off[128];
    const int t = threadIdx.x;
    if (t < 32) {
        const int base = t * 4;
        int c0 = (base + 0 < SCAN_BLK) ? g_blk[base + 0] : 0;
        int c1 = (base + 1 < SCAN_BLK) ? g_blk[base + 1] : 0;
        int c2 = (base + 2 < SCAN_BLK) ? g_blk[base + 2] : 0;
        int c3 = (base + 3 < SCAN_BLK) ? g_blk[base + 3] : 0;
        int tsum = c0 + c1 + c2 + c3;
        int incl = tsum;
#pragma unroll
        for (int o = 1; o < 32; o <<= 1) {
            int u = __shfl_up_sync(0xffffffffu, incl, o);
            if (t >= o) incl += u;
        }
        int excl = incl - tsum;
        off[base + 0] = excl;
        off[base + 1] = excl + c0;
        off[base + 2] = excl + c0 + c1;
        off[base + 3] = excl + c0 + c1 + c2;
    }
    __syncthreads();
    const int stride = gridDim.x * blockDim.x;
    for (int i = blockIdx.x * blockDim.x + t; i < N_NODES; i += stride) {
        int p = g_ptr[i] + off[i >> 10];
        g_ptr[i] = p;
        g_cur[i] = p;
    }
    if (blockIdx.x == 0 && t == 0) g_ptr[N_NODES] = N_EDGES;
}

// ---------------- scatter edges into CSR order (4 edges/thread, packed) -----------
__global__ void scatter_kernel(const int* __restrict__ ei, const float* __restrict__ ea) {
    const int q = blockIdx.x * blockDim.x + threadIdx.x;
    if (q >= N_EDGES / 4) return;
    int4 r = __ldg(&((const int4*)ei)[q]);
    int4 c = __ldg(&((const int4*)(ei + N_EDGES))[q]);
    float4 v = __ldg(&((const float4*)ea)[q]);
    int p0 = atomicAdd(&g_cur[r.x], 1);
    int p1 = atomicAdd(&g_cur[r.y], 1);
    int p2 = atomicAdd(&g_cur[r.z], 1);
    int p3 = atomicAdd(&g_cur[r.w], 1);
    g_edge[p0] = ((unsigned long long)__float_as_uint(v.x) << 32) | (unsigned int)c.x;
    g_edge[p1] = ((unsigned long long)__float_as_uint(v.y) << 32) | (unsigned int)c.y;
    g_edge[p2] = ((unsigned long long)__float_as_uint(v.z) << 32) | (unsigned int)c.z;
    g_edge[p3] = ((unsigned long long)__float_as_uint(v.w) << 32) | (unsigned int)c.w;
}

// ---------------- tensor-core GEMM: H = fp16( x @ [W0|W1] ) ----------------
#define SM_STRIDE 136

__device__ __forceinline__ unsigned int smem_u32(const void* p) {
    unsigned int a;
    asm("{ .reg .u64 t; cvta.to.shared.u64 t, %1; cvt.u32.u64 %0, t; }"
        : "=r"(a) : "l"(p));
    return a;
}

__global__ __launch_bounds__(256) void gemm_kernel(const float* __restrict__ x,
                                                   const float* __restrict__ W0,
                                                   const float* __restrict__ W1) {
    extern __shared__ __half smem_dyn[];
    __half* As = smem_dyn;                         // [128][SM_STRIDE]
    __half* Bs = smem_dyn + 128 * SM_STRIDE;       // [128][SM_STRIDE]

    const int tid = threadIdx.x;
    const int r0 = blockIdx.x * 128;

    const float4* W04 = (const float4*)W0;
    const float4* W14 = (const float4*)W1;
    for (int i = tid; i < 2048; i += 256) {
        int k = i >> 4, c4 = i & 15;
        float4 v0 = __ldg(&W04[i]);
        float4 v1 = __ldg(&W14[i]);
        __half2 a01 = __floats2half2_rn(v0.x, v0.y);
        __half2 a23 = __floats2half2_rn(v0.z, v0.w);
        __half2 b01 = __floats2half2_rn(v1.x, v1.y);
        __half2 b23 = __floats2half2_rn(v1.z, v1.w);
        *(uint2*)&Bs[k * SM_STRIDE + c4 * 4] =
            make_uint2(*(unsigned int*)&a01, *(unsigned int*)&a23);
        *(uint2*)&Bs[k * SM_STRIDE + 64 + c4 * 4] =
            make_uint2(*(unsigned int*)&b01, *(unsigned int*)&b23);
    }
    const float4* x4 = (const float4*)x;
    for (int i = tid; i < 4096; i += 256) {
        int r = i >> 5, c4 = i & 31;
        float4 v = (r0 + r < N_NODES) ? __ldg(&x4[(size_t)(r0 + r) * 32 + c4])
                                      : make_float4(0.f, 0.f, 0.f, 0.f);
        __half2 h01 = __floats2half2_rn(v.x, v.y);
        __half2 h23 = __floats2half2_rn(v.z, v.w);
        *(uint2*)&As[r * SM_STRIDE + c4 * 4] =
            make_uint2(*(unsigned int*)&h01, *(unsigned int*)&h23);
    }
    __syncthreads();

    const int w = tid >> 5;
    const int lane = tid & 31;
    const unsigned int As_u = smem_u32(As);
    const unsigned int Bs_u = smem_u32(Bs);

    const int arow = w * 16 + (lane & 7) + (lane & 8);
    const int acol8 = (lane >> 4) & 1;
    const int bls = lane & 15;

    float acc[16][4];
#pragma unroll
    for (int n = 0; n < 16; n++)
#pragma unroll
        for (int c = 0; c < 4; c++) acc[n][c] = 0.f;

#pragma unroll
    for (int kk = 0; kk < 8; kk++) {
        unsigned int a0, a1, a2, a3;
        unsigned int addrA = As_u + (unsigned int)((arow * SM_STRIDE + kk * 16 + acol8 * 8) * 2);
        asm volatile("ldmatrix.sync.aligned.m8n8.x4.shared.b16 {%0,%1,%2,%3}, [%4];"
                     : "=r"(a0), "=r"(a1), "=r"(a2), "=r"(a3) : "r"(addrA));
        unsigned int addrB0 = Bs_u + (unsigned int)(((kk * 16 + bls) * SM_STRIDE) * 2);
#pragma unroll
        for (int n = 0; n < 16; n++) {
            unsigned int bm0, bm1;
            unsigned int addrB = addrB0 + (unsigned int)(n * 16);
            asm volatile("ldmatrix.sync.aligned.m8n8.x2.trans.shared.b16 {%0,%1}, [%2];"
                         : "=r"(bm0), "=r"(bm1) : "r"(addrB));
            asm volatile(
                "mma.sync.aligned.m16n8k16.row.col.f32.f16.f16.f32 "
                "{%0,%1,%2,%3}, {%4,%5,%6,%7}, {%8,%9}, {%0,%1,%2,%3};"
                : "+f"(acc[n][0]), "+f"(acc[n][1]), "+f"(acc[n][2]), "+f"(acc[n][3])
                : "r"(a0), "r"(a1), "r"(a2), "r"(a3), "r"(bm0), "r"(bm1));
        }
    }

    const int rA = r0 + w * 16 + (lane >> 2);
    const int colb = (lane & 3) * 2;
#pragma unroll
    for (int n = 0; n < 16; n++) {
        int col = n * 8 + colb;
        if (rA < N_NODES) {
            __half2 h = __floats2half2_rn(acc[n][0], acc[n][1]);
            *(__half2*)&g_H[(size_t)rA * 128 + col] = h;
        }
        if (rA + 8 < N_NODES) {
            __half2 h = __floats2half2_rn(acc[n][2], acc[n][3]);
            *(__half2*)&g_H[(size_t)(rA + 8) * 128 + col] = h;
        }
    }
}

// ---------------- host-side stream/event objects (created once at load) ----------
namespace {
struct ForkCtx {
    cudaStream_t s2;
    cudaEvent_t evF, evG, evC, evH;
    ForkCtx() {
        cudaStreamCreateWithFlags(&s2, cudaStreamNonBlocking);
        cudaEventCreateWithFlags(&evF, cudaEventDisableTiming);
        cudaEventCreateWithFlags(&evG, cudaEventDisableTiming);
        cudaEventCreateWithFlags(&evC, cudaEventDisableTiming);
        cudaEventCreateWithFlags(&evH, cudaEventDisableTiming);
        cudaFuncSetAttribute(gemm_kernel, cudaFuncAttributeMaxDynamicSharedMemorySize,
                             2 * 128 * SM_STRIDE * (int)sizeof(__half));
    }
};
ForkCtx g_fork;
}

// ---------------- SpMM helpers ----------------
__device__ __forceinline__ void unpack_edge(unsigned long long p, int& c, float& v) {
    c = (int)(unsigned int)p;
    v = __uint_as_float((unsigned int)(p >> 32));
}
__device__ __forceinline__ float2 ld_half2f(const __half* p) {
    unsigned int u = *(const unsigned int*)p;
    return __half22float2(*(__half2*)&u);
}

// generic warp-per-row gather-sum over a half-typed table with row stride (halves).
// acc: float2 per lane (cols 2*lane, 2*lane+1). deg accumulates sum(v * dval),
// where dval = 1 (DEGMODE 1) or g_deg1[c] (DEGMODE 2).
template <int STRIDE_H, int OFF_H, int DEGMODE>
__device__ __forceinline__ void gather_row(const __half* table, int s, int e, int lane,
                                           float2& acc, float& deg) {
    int i = s;
    const int n8 = s + ((e - s) & ~7);
    for (; i < n8; i += 8) {
        int c[8];
        float v[8];
#pragma unroll
        for (int k = 0; k < 8; k++) unpack_edge(g_edge[i + k], c[k], v[k]);
        float2 t[8];
#pragma unroll
        for (int k = 0; k < 8; k++)
            t[k] = ld_half2f(&table[(size_t)c[k] * STRIDE_H + OFF_H + lane * 2]);
#pragma unroll
        for (int k = 0; k < 8; k++) {
            acc.x += v[k] * t[k].x;
            acc.y += v[k] * t[k].y;
            if (DEGMODE == 1) deg += v[k];
            else              deg += v[k] * __ldg(&g_deg1[c[k]]);
        }
    }
    for (; i < e; i++) {
        int c;
        float v;
        unpack_edge(g_edge[i], c, v);
        float2 t = ld_half2f(&table[(size_t)c * STRIDE_H + OFF_H + lane * 2]);
        acc.x += v * t.x;
        acc.y += v * t.y;
        if (DEGMODE == 1) deg += v;
        else              deg += v * __ldg(&g_deg1[c]);
    }
}

// shared epilogue: normalize, bias, adaptive encode, write 64 floats.
__device__ __forceinline__ void epilogue(int w, int lane, float2 acc, float deg,
                                         const float* __restrict__ b,
                                         const float* __restrict__ fc,
                                         const float* __restrict__ bf,
                                         float* __restrict__ out, int col0) {
    float inv = (deg > 0.f) ? (1.f / deg) : 0.f;
    float2 y;
    y.x = acc.x * inv + __ldg(&b[2 * lane]);
    y.y = acc.y * inv + __ldg(&b[2 * lane + 1]);
    float dot = y.x * __ldg(&fc[2 * lane]) + y.y * __ldg(&fc[2 * lane + 1]);
#pragma unroll
    for (int o = 16; o; o >>= 1) dot += __shfl_xor_sync(0xffffffffu, dot, o);
    float g = 1.f / (1.f + expf(-(dot + __ldg(&bf[0]))));
    float2 o;
    o.x = (y.x > 0.f) ? y.x : g * y.x;
    o.y = (y.y > 0.f) ? y.y : g * y.y;
    *(float2*)&out[(size_t)w * 128 + col0 + 2 * lane] = o;
}

// ---- hop0: gather h0 half of H, epilogue -> out[:,0:64]  (side stream) ----------
__global__ __launch_bounds__(256) void spmm_h0_kernel(const float* __restrict__ b0,
                                                      const float* __restrict__ fc0,
                                                      const float* __restrict__ bf0,
                                                      float* __restrict__ out) {
    const int w = (blockIdx.x * 256 + threadIdx.x) >> 5;
    const int lane = threadIdx.x & 31;
    if (w >= N_NODES) return;
    const int s = g_ptr[w];
    const int e = g_ptr[w + 1];
    float2 acc = make_float2(0.f, 0.f);
    float deg = 0.f;
    gather_row<128, 0, 1>(g_H, s, e, lane, acc, deg);
    epilogue(w, lane, acc, deg, b0, fc0, bf0, out, 0);
}

// ---- T pass: gather h1 half of H -> g_T (fp16), g_deg1  (main stream) -----------
__global__ __launch_bounds__(256) void spmm_T_kernel() {
    const int w = (blockIdx.x * 256 + threadIdx.x) >> 5;
    const int lane = threadIdx.x & 31;
    if (w >= N_NODES) return;
    const int s = g_ptr[w];
    const int e = g_ptr[w + 1];
    float2 acc = make_float2(0.f, 0.f);
    float deg = 0.f;
    gather_row<128, 64, 1>(g_H, s, e, lane, acc, deg);
    __half2 h = __floats2half2_rn(acc.x, acc.y);
    *(__half2*)&g_T[(size_t)w * 64 + 2 * lane] = h;
    if (lane == 0) g_deg1[w] = deg;
}

// ---- hop1: gather T, epilogue -> out[:,64:128]  (main stream) --------------------
__global__ __launch_bounds__(256) void spmm2_kernel(const float* __restrict__ b1,
                                                    const float* __restrict__ fc1,
                                                    const float* __restrict__ bf1,
                                                    float* __restrict__ out) {
    const int w = (blockIdx.x * 256 + threadIdx.x) >> 5;
    const int lane = threadIdx.x & 31;
    if (w >= N_NODES) return;
    const int s = g_ptr[w];
    const int e = g_ptr[w + 1];
    float2 acc = make_float2(0.f, 0.f);
    float deg = 0.f;
    gather_row<64, 0, 2>(g_T, s, e, lane, acc, deg);
    epilogue(w, lane, acc, deg, b1, fc1, bf1, out, 64);
}

// ---------------- launch ----------------
extern "C" void kernel_launch(void* const* d_in, const int* in_sizes, int n_in,
                              void* d_out, int out_size) {
    const float* x   = (const float*)d_in[0];
    const int*   ei  = (const int*)d_in[1];
    const float* ea  = (const float*)d_in[2];
    const float* W0  = (const float*)d_in[3];
    const float* b0  = (const float*)d_in[4];
    const float* W1  = (const float*)d_in[5];
    const float* b1  = (const float*)d_in[6];
    const float* fc0 = (const float*)d_in[7];
    const float* bf0 = (const float*)d_in[8];
    const float* fc1 = (const float*)d_in[9];
    const float* bf1 = (const float*)d_in[10];
    float* out = (float*)d_out;

    const int spmm_blocks = (N_NODES * 32 + 255) / 256;

    // fork: GEMM on s2, CSR build on main
    cudaEventRecord(g_fork.evF, 0);
    cudaStreamWaitEvent(g_fork.s2, g_fork.evF, 0);

    const int gemm_smem = 2 * 128 * SM_STRIDE * (int)sizeof(__half);
    gemm_kernel<<<(N_NODES + 127) / 128, 256, gemm_smem, g_fork.s2>>>(x, W0, W1);
    cudaEventRecord(g_fork.evG, g_fork.s2);

    hist_kernel<<<512, 256>>>(ei);
    scan1_kernel<<<SCAN_BLK, 256>>>();
    scan3_kernel<<<392, 256>>>();
    scatter_kernel<<<(N_EDGES / 4 + 255) / 256, 256>>>(ei, ea);
    cudaEventRecord(g_fork.evC, 0);

    // main: needs g_H (evG) for spmm_T; then spmm2
    cudaStreamWaitEvent(0, g_fork.evG, 0);
    spmm_T_kernel<<<spmm_blocks, 256>>>();
    spmm2_kernel<<<spmm_blocks, 256>>>(b1, fc1, bf1, out);

    // s2: needs CSR (evC); g_H already in-stream after gemm
    cudaStreamWaitEvent(g_fork.s2, g_fork.evC, 0);
    spmm_h0_kernel<<<spmm_blocks, 256, 0, g_fork.s2>>>(b0, fc0, bf0, out);
    cudaEventRecord(g_fork.evH, g_fork.s2);

    // join: all of d_out written
    cudaStreamWaitEvent(0, g_fork.evH, 0);
}

// round 12
// speedup vs baseline: 1.0828x; 1.0828x over previous
#include <cuda_runtime.h>
#include <cuda_fp16.h>
#include <cstdint>
#include <math.h>

#define N_NODES 100000
#define N_EDGES 1000000
#define SCAN_BLK 98               // ceil(100000 / 1024)

// ---------------- scratch (static device globals; no allocation) ----------------
__device__ __half g_H[(size_t)N_NODES * 128];   // [N][128] fp16 : x@W0 | x@W1
__device__ __half g_T[(size_t)N_NODES * 64];    // [N][64]  fp16 : A h1
__device__ float  g_deg1[N_NODES];              // A 1

// CSR build scratch (zero at load; g_cnt re-zeroed by scan, flags by scatter)
__device__ int   g_cnt[N_NODES];
__device__ int   g_cur[N_NODES];                // scatter cursors (init = row ptr)
__device__ int   g_ptr[N_NODES + 1];            // row_ptr (exclusive)
__device__ int   g_blk[128];                    // block sums
__device__ int   g_flag[128];                   // block-sum ready flags
__device__ unsigned long long g_edge[N_EDGES];  // packed {val_bits:32 | col:32}

// ---------------- histogram of rows ----------------
__global__ void hist_kernel(const int* __restrict__ ei) {
    const int stride = gridDim.x * blockDim.x;
    const int4* R4 = (const int4*)ei;
    for (int i = blockIdx.x * blockDim.x + threadIdx.x; i < N_EDGES / 4; i += stride) {
        int4 r = __ldg(&R4[i]);
        atomicAdd(&g_cnt[r.x], 1);
        atomicAdd(&g_cnt[r.y], 1);
        atomicAdd(&g_cnt[r.z], 1);
        atomicAdd(&g_cnt[r.w], 1);
    }
}

// ---- single-pass scan with release/acquire inter-block handshake. ---------------
// 98 blocks (<148 SMs) are all co-resident -> polling cannot deadlock.
// Producer: write g_blk, then st.release flag. Consumer: ld.acquire flag,
// which orders the following g_blk read. Flags reset by scatter (stream order).
__global__ __launch_bounds__(256) void scan_kernel() {
    __shared__ int sh[256];
    __shared__ int prev_sum;
    const int t = threadIdx.x;
    const int b = blockIdx.x;
    const int base = b * 1024 + t * 4;
    int c0 = (base + 0 < N_NODES) ? g_cnt[base + 0] : 0;
    int c1 = (base + 1 < N_NODES) ? g_cnt[base + 1] : 0;
    int c2 = (base + 2 < N_NODES) ? g_cnt[base + 2] : 0;
    int c3 = (base + 3 < N_NODES) ? g_cnt[base + 3] : 0;
    if (base + 0 < N_NODES) g_cnt[base + 0] = 0;   // re-zero for next call
    if (base + 1 < N_NODES) g_cnt[base + 1] = 0;
    if (base + 2 < N_NODES) g_cnt[base + 2] = 0;
    if (base + 3 < N_NODES) g_cnt[base + 3] = 0;
    int tsum = c0 + c1 + c2 + c3;
    sh[t] = tsum;
    if (t == 0) prev_sum = 0;
    __syncthreads();
    for (int off = 1; off < 256; off <<= 1) {
        int v = (t >= off) ? sh[t - off] : 0;
        __syncthreads();
        if (t >= off) sh[t] += v;
        __syncthreads();
    }
    int excl = (t > 0) ? sh[t - 1] : 0;

    // publish this block's total with release; consume predecessors with acquire
    if (t == 255) {
        g_blk[b] = sh[255];
        asm volatile("st.release.gpu.global.b32 [%0], %1;"
                     :: "l"(&g_flag[b]), "r"(1) : "memory");
    }
    if (t < b) {                                   // b <= 97 < 256
        int f;
        do {
            asm volatile("ld.acquire.gpu.global.b32 %0, [%1];"
                         : "=r"(f) : "l"(&g_flag[t]) : "memory");
        } while (f == 0);
        atomicAdd(&prev_sum, g_blk[t]);
    }
    __syncthreads();
    const int off0 = prev_sum;

    int p0 = off0 + excl;
    if (base + 0 < N_NODES) { g_ptr[base + 0] = p0;           g_cur[base + 0] = p0; }
    if (base + 1 < N_NODES) { g_ptr[base + 1] = p0 + c0;      g_cur[base + 1] = p0 + c0; }
    if (base + 2 < N_NODES) { g_ptr[base + 2] = p0 + c0 + c1; g_cur[base + 2] = p0 + c0 + c1; }
    if (base + 3 < N_NODES) { g_ptr[base + 3] = p0 + c0 + c1 + c2;
                              g_cur[base + 3] = p0 + c0 + c1 + c2; }
    if (b == 0 && t == 0) g_ptr[N_NODES] = N_EDGES;
}

// ---------------- scatter edges into CSR order; also reset scan flags -----------
__global__ void scatter_kernel(const int* __restrict__ ei, const float* __restrict__ ea) {
    const int q = blockIdx.x * blockDim.x + threadIdx.x;
    if (q < 128) g_flag[q] = 0;                    // reset for next launch/replay
    if (q >= N_EDGES / 4) return;
    int4 r = __ldg(&((const int4*)ei)[q]);
    int4 c = __ldg(&((const int4*)(ei + N_EDGES))[q]);
    float4 v = __ldg(&((const float4*)ea)[q]);
    int p0 = atomicAdd(&g_cur[r.x], 1);
    int p1 = atomicAdd(&g_cur[r.y], 1);
    int p2 = atomicAdd(&g_cur[r.z], 1);
    int p3 = atomicAdd(&g_cur[r.w], 1);
    g_edge[p0] = ((unsigned long long)__float_as_uint(v.x) << 32) | (unsigned int)c.x;
    g_edge[p1] = ((unsigned long long)__float_as_uint(v.y) << 32) | (unsigned int)c.y;
    g_edge[p2] = ((unsigned long long)__float_as_uint(v.z) << 32) | (unsigned int)c.z;
    g_edge[p3] = ((unsigned long long)__float_as_uint(v.w) << 32) | (unsigned int)c.w;
}

// ---------------- tensor-core GEMM: H = fp16( x @ [W0|W1] ) ----------------
#define SM_STRIDE 136

__device__ __forceinline__ unsigned int smem_u32(const void* p) {
    unsigned int a;
    asm("{ .reg .u64 t; cvta.to.shared.u64 t, %1; cvt.u32.u64 %0, t; }"
        : "=r"(a) : "l"(p));
    return a;
}

__global__ __launch_bounds__(256) void gemm_kernel(const float* __restrict__ x,
                                                   const float* __restrict__ W0,
                                                   const float* __restrict__ W1) {
    extern __shared__ __half smem_dyn[];
    __half* As = smem_dyn;                         // [128][SM_STRIDE]
    __half* Bs = smem_dyn + 128 * SM_STRIDE;       // [128][SM_STRIDE]

    const int tid = threadIdx.x;
    const int r0 = blockIdx.x * 128;

    const float4* W04 = (const float4*)W0;
    const float4* W14 = (const float4*)W1;
    for (int i = tid; i < 2048; i += 256) {
        int k = i >> 4, c4 = i & 15;
        float4 v0 = __ldg(&W04[i]);
        float4 v1 = __ldg(&W14[i]);
        __half2 a01 = __floats2half2_rn(v0.x, v0.y);
        __half2 a23 = __floats2half2_rn(v0.z, v0.w);
        __half2 b01 = __floats2half2_rn(v1.x, v1.y);
        __half2 b23 = __floats2half2_rn(v1.z, v1.w);
        *(uint2*)&Bs[k * SM_STRIDE + c4 * 4] =
            make_uint2(*(unsigned int*)&a01, *(unsigned int*)&a23);
        *(uint2*)&Bs[k * SM_STRIDE + 64 + c4 * 4] =
            make_uint2(*(unsigned int*)&b01, *(unsigned int*)&b23);
    }
    const float4* x4 = (const float4*)x;
    for (int i = tid; i < 4096; i += 256) {
        int r = i >> 5, c4 = i & 31;
        float4 v = (r0 + r < N_NODES) ? __ldg(&x4[(size_t)(r0 + r) * 32 + c4])
                                      : make_float4(0.f, 0.f, 0.f, 0.f);
        __half2 h01 = __floats2half2_rn(v.x, v.y);
        __half2 h23 = __floats2half2_rn(v.z, v.w);
        *(uint2*)&As[r * SM_STRIDE + c4 * 4] =
            make_uint2(*(unsigned int*)&h01, *(unsigned int*)&h23);
    }
    __syncthreads();

    const int w = tid >> 5;
    const int lane = tid & 31;
    const unsigned int As_u = smem_u32(As);
    const unsigned int Bs_u = smem_u32(Bs);

    const int arow = w * 16 + (lane & 7) + (lane & 8);
    const int acol8 = (lane >> 4) & 1;
    const int bls = lane & 15;

    float acc[16][4];
#pragma unroll
    for (int n = 0; n < 16; n++)
#pragma unroll
        for (int c = 0; c < 4; c++) acc[n][c] = 0.f;

#pragma unroll
    for (int kk = 0; kk < 8; kk++) {
        unsigned int a0, a1, a2, a3;
        unsigned int addrA = As_u + (unsigned int)((arow * SM_STRIDE + kk * 16 + acol8 * 8) * 2);
        asm volatile("ldmatrix.sync.aligned.m8n8.x4.shared.b16 {%0,%1,%2,%3}, [%4];"
                     : "=r"(a0), "=r"(a1), "=r"(a2), "=r"(a3) : "r"(addrA));
        unsigned int addrB0 = Bs_u + (unsigned int)(((kk * 16 + bls) * SM_STRIDE) * 2);
#pragma unroll
        for (int n = 0; n < 16; n++) {
            unsigned int bm0, bm1;
            unsigned int addrB = addrB0 + (unsigned int)(n * 16);
            asm volatile("ldmatrix.sync.aligned.m8n8.x2.trans.shared.b16 {%0,%1}, [%2];"
                         : "=r"(bm0), "=r"(bm1) : "r"(addrB));
            asm volatile(
                "mma.sync.aligned.m16n8k16.row.col.f32.f16.f16.f32 "
                "{%0,%1,%2,%3}, {%4,%5,%6,%7}, {%8,%9}, {%0,%1,%2,%3};"
                : "+f"(acc[n][0]), "+f"(acc[n][1]), "+f"(acc[n][2]), "+f"(acc[n][3])
                : "r"(a0), "r"(a1), "r"(a2), "r"(a3), "r"(bm0), "r"(bm1));
        }
    }

    const int rA = r0 + w * 16 + (lane >> 2);
    const int colb = (lane & 3) * 2;
#pragma unroll
    for (int n = 0; n < 16; n++) {
        int col = n * 8 + colb;
        if (rA < N_NODES) {
            __half2 h = __floats2half2_rn(acc[n][0], acc[n][1]);
            *(__half2*)&g_H[(size_t)rA * 128 + col] = h;
        }
        if (rA + 8 < N_NODES) {
            __half2 h = __floats2half2_rn(acc[n][2], acc[n][3]);
            *(__half2*)&g_H[(size_t)(rA + 8) * 128 + col] = h;
        }
    }
}

// ---------------- host-side stream/event objects (created once at load) ----------
namespace {
struct ForkCtx {
    cudaStream_t s2;
    cudaEvent_t evF, evG, evH;
    ForkCtx() {
        cudaStreamCreateWithFlags(&s2, cudaStreamNonBlocking);
        cudaEventCreateWithFlags(&evF, cudaEventDisableTiming);
        cudaEventCreateWithFlags(&evG, cudaEventDisableTiming);
        cudaEventCreateWithFlags(&evH, cudaEventDisableTiming);
        cudaFuncSetAttribute(gemm_kernel, cudaFuncAttributeMaxDynamicSharedMemorySize,
                             2 * 128 * SM_STRIDE * (int)sizeof(__half));
    }
};
ForkCtx g_fork;
}

// ---------------- SpMM helpers ----------------
__device__ __forceinline__ void unpack_edge(unsigned long long p, int& c, float& v) {
    c = (int)(unsigned int)p;
    v = __uint_as_float((unsigned int)(p >> 32));
}
__device__ __forceinline__ float4 ld_half4(const __half* p) {
    uint2 u = *(const uint2*)p;
    float2 a = __half22float2(*(__half2*)&u.x);
    float2 b = __half22float2(*(__half2*)&u.y);
    return make_float4(a.x, a.y, b.x, b.y);
}

// ---- pass 1 + hop0 epilogue: warp per row, 4-edge unroll, fp16 gathers -----------
// lanes 0-15 : hop0 features (cols 0..63) -> normalize+encode -> out[:,0:64]
// lanes 16-31: hop1 partial T = A h1      -> fp16 store to g_T
__global__ __launch_bounds__(256) void spmm1_kernel(const float* __restrict__ b0,
                                                    const float* __restrict__ fc0,
                                                    const float* __restrict__ bf0,
                                                    float* __restrict__ out) {
    const int w = (blockIdx.x * 256 + threadIdx.x) >> 5;
    const int lane = threadIdx.x & 31;
    if (w >= N_NODES) return;
    const int s = g_ptr[w];
    const int e = g_ptr[w + 1];

    float4 acc = make_float4(0.f, 0.f, 0.f, 0.f);
    float deg = 0.f;
    int i = s;
    for (; i + 4 <= e; i += 4) {
        int c0, c1, c2, c3;
        float v0, v1, v2, v3;
        unpack_edge(g_edge[i + 0], c0, v0);
        unpack_edge(g_edge[i + 1], c1, v1);
        unpack_edge(g_edge[i + 2], c2, v2);
        unpack_edge(g_edge[i + 3], c3, v3);
        float4 h0 = ld_half4(&g_H[(size_t)c0 * 128 + lane * 4]);
        float4 h1 = ld_half4(&g_H[(size_t)c1 * 128 + lane * 4]);
        float4 h2 = ld_half4(&g_H[(size_t)c2 * 128 + lane * 4]);
        float4 h3 = ld_half4(&g_H[(size_t)c3 * 128 + lane * 4]);
        acc.x += v0 * h0.x + v1 * h1.x + v2 * h2.x + v3 * h3.x;
        acc.y += v0 * h0.y + v1 * h1.y + v2 * h2.y + v3 * h3.y;
        acc.z += v0 * h0.z + v1 * h1.z + v2 * h2.z + v3 * h3.z;
        acc.w += v0 * h0.w + v1 * h1.w + v2 * h2.w + v3 * h3.w;
        deg += (v0 + v1) + (v2 + v3);
    }
    if (i + 2 <= e) {
        int c0, c1;
        float v0, v1;
        unpack_edge(g_edge[i + 0], c0, v0);
        unpack_edge(g_edge[i + 1], c1, v1);
        float4 h0 = ld_half4(&g_H[(size_t)c0 * 128 + lane * 4]);
        float4 h1 = ld_half4(&g_H[(size_t)c1 * 128 + lane * 4]);
        acc.x += v0 * h0.x + v1 * h1.x;
        acc.y += v0 * h0.y + v1 * h1.y;
        acc.z += v0 * h0.z + v1 * h1.z;
        acc.w += v0 * h0.w + v1 * h1.w;
        deg += v0 + v1;
        i += 2;
    }
    if (i < e) {
        int c0;
        float v0;
        unpack_edge(g_edge[i], c0, v0);
        float4 h0 = ld_half4(&g_H[(size_t)c0 * 128 + lane * 4]);
        acc.x += v0 * h0.x;
        acc.y += v0 * h0.y;
        acc.z += v0 * h0.z;
        acc.w += v0 * h0.w;
        deg += v0;
    }

    const int l4 = (lane & 15) * 4;
    float inv = (deg > 0.f) ? (1.f / deg) : 0.f;
    float4 y;
    y.x = acc.x * inv + __ldg(&b0[l4 + 0]);
    y.y = acc.y * inv + __ldg(&b0[l4 + 1]);
    y.z = acc.z * inv + __ldg(&b0[l4 + 2]);
    y.w = acc.w * inv + __ldg(&b0[l4 + 3]);
    float dot = y.x * __ldg(&fc0[l4 + 0]) + y.y * __ldg(&fc0[l4 + 1]) +
                y.z * __ldg(&fc0[l4 + 2]) + y.w * __ldg(&fc0[l4 + 3]);
#pragma unroll
    for (int o = 8; o; o >>= 1) dot += __shfl_xor_sync(0xffffffffu, dot, o);
    float g = 1.f / (1.f + expf(-(dot + __ldg(&bf0[0]))));

    if (lane < 16) {
        float4 o;
        o.x = (y.x > 0.f) ? y.x : g * y.x;
        o.y = (y.y > 0.f) ? y.y : g * y.y;
        o.z = (y.z > 0.f) ? y.z : g * y.z;
        o.w = (y.w > 0.f) ? y.w : g * y.w;
        *(float4*)&out[(size_t)w * 128 + l4] = o;
    } else {
        __half2 t0 = __floats2half2_rn(acc.x, acc.y);
        __half2 t1 = __floats2half2_rn(acc.z, acc.w);
        *(uint2*)&g_T[(size_t)w * 64 + l4] =
            make_uint2(*(unsigned int*)&t0, *(unsigned int*)&t1);
    }
    if (lane == 0) g_deg1[w] = deg;
}

// ---- pass 2 + hop1 epilogue: warp per row, 4-edge unroll, fp16 T gathers ----------
__global__ __launch_bounds__(256) void spmm2_kernel(const float* __restrict__ b1,
                                                    const float* __restrict__ fc1,
                                                    const float* __restrict__ bf1,
                                                    float* __restrict__ out) {
    const int w = (blockIdx.x * 256 + threadIdx.x) >> 5;
    const int lane = threadIdx.x & 31;
    if (w >= N_NODES) return;
    const int s = g_ptr[w];
    const int e = g_ptr[w + 1];

    float2 acc = make_float2(0.f, 0.f);
    float deg = 0.f;
    int i = s;
    for (; i + 4 <= e; i += 4) {
        int c0, c1, c2, c3;
        float v0, v1, v2, v3;
        unpack_edge(g_edge[i + 0], c0, v0);
        unpack_edge(g_edge[i + 1], c1, v1);
        unpack_edge(g_edge[i + 2], c2, v2);
        unpack_edge(g_edge[i + 3], c3, v3);
        unsigned int u0 = *(const unsigned int*)&g_T[(size_t)c0 * 64 + lane * 2];
        unsigned int u1 = *(const unsigned int*)&g_T[(size_t)c1 * 64 + lane * 2];
        unsigned int u2 = *(const unsigned int*)&g_T[(size_t)c2 * 64 + lane * 2];
        unsigned int u3 = *(const unsigned int*)&g_T[(size_t)c3 * 64 + lane * 2];
        float d0 = __ldg(&g_deg1[c0]);
        float d1 = __ldg(&g_deg1[c1]);
        float d2 = __ldg(&g_deg1[c2]);
        float d3 = __ldg(&g_deg1[c3]);
        float2 t0 = __half22float2(*(__half2*)&u0);
        float2 t1 = __half22float2(*(__half2*)&u1);
        float2 t2 = __half22float2(*(__half2*)&u2);
        float2 t3 = __half22float2(*(__half2*)&u3);
        acc.x += v0 * t0.x + v1 * t1.x + v2 * t2.x + v3 * t3.x;
        acc.y += v0 * t0.y + v1 * t1.y + v2 * t2.y + v3 * t3.y;
        deg += (v0 * d0 + v1 * d1) + (v2 * d2 + v3 * d3);
    }
    if (i + 2 <= e) {
        int c0, c1;
        float v0, v1;
        unpack_edge(g_edge[i + 0], c0, v0);
        unpack_edge(g_edge[i + 1], c1, v1);
        unsigned int u0 = *(const unsigned int*)&g_T[(size_t)c0 * 64 + lane * 2];
        unsigned int u1 = *(const unsigned int*)&g_T[(size_t)c1 * 64 + lane * 2];
        float2 t0 = __half22float2(*(__half2*)&u0);
        float2 t1 = __half22float2(*(__half2*)&u1);
        acc.x += v0 * t0.x + v1 * t1.x;
        acc.y += v0 * t0.y + v1 * t1.y;
        deg += v0 * __ldg(&g_deg1[c0]) + v1 * __ldg(&g_deg1[c1]);
        i += 2;
    }
    if (i < e) {
        int c0;
        float v0;
        unpack_edge(g_edge[i], c0, v0);
        unsigned int u0 = *(const unsigned int*)&g_T[(size_t)c0 * 64 + lane * 2];
        float2 t0 = __half22float2(*(__half2*)&u0);
        acc.x += v0 * t0.x;
        acc.y += v0 * t0.y;
        deg += v0 * __ldg(&g_deg1[c0]);
    }

    float inv = (deg > 0.f) ? (1.f / deg) : 0.f;
    float2 y;
    y.x = acc.x * inv + __ldg(&b1[2 * lane]);
    y.y = acc.y * inv + __ldg(&b1[2 * lane + 1]);
    float dot = y.x * __ldg(&fc1[2 * lane]) + y.y * __ldg(&fc1[2 * lane + 1]);
#pragma unroll
    for (int o = 16; o; o >>= 1) dot += __shfl_xor_sync(0xffffffffu, dot, o);
    float g = 1.f / (1.f + expf(-(dot + __ldg(&bf1[0]))));

    float2 o;
    o.x = (y.x > 0.f) ? y.x : g * y.x;
    o.y = (y.y > 0.f) ? y.y : g * y.y;
    *(float2*)&out[(size_t)w * 128 + 64 + 2 * lane] = o;
}

// ---------------- launch ----------------
extern "C" void kernel_launch(void* const* d_in, const int* in_sizes, int n_in,
                              void* d_out, int out_size) {
    const float* x   = (const float*)d_in[0];
    const int*   ei  = (const int*)d_in[1];
    const float* ea  = (const float*)d_in[2];
    const float* W0  = (const float*)d_in[3];
    const float* b0  = (const float*)d_in[4];
    const float* W1  = (const float*)d_in[5];
    const float* b1  = (const float*)d_in[6];
    const float* fc0 = (const float*)d_in[7];
    const float* bf0 = (const float*)d_in[8];
    const float* fc1 = (const float*)d_in[9];
    const float* bf1 = (const float*)d_in[10];
    float* out = (float*)d_out;

    // Fork: GEMM on side stream, CSR build on main stream (independent chains).
    cudaEventRecord(g_fork.evF, 0);
    cudaStreamWaitEvent(g_fork.s2, g_fork.evF, 0);

    const int gemm_smem = 2 * 128 * SM_STRIDE * (int)sizeof(__half);
    gemm_kernel<<<(N_NODES + 127) / 128, 256, gemm_smem, g_fork.s2>>>(x, W0, W1);
    cudaEventRecord(g_fork.evG, g_fork.s2);

    hist_kernel<<<512, 256>>>(ei);
    scan_kernel<<<SCAN_BLK, 256>>>();
    scatter_kernel<<<(N_EDGES / 4 + 255) / 256, 256>>>(ei, ea);

    // Join: spmm1 needs both the CSR (main stream) and g_H (side stream).
    cudaStreamWaitEvent(0, g_fork.evG, 0);

    spmm1_kernel<<<(N_NODES * 32 + 255) / 256, 256>>>(b0, fc0, bf0, out);
    spmm2_kernel<<<(N_NODES * 32 + 255) / 256, 256>>>(b1, fc1, bf1, out);
}